// round 14
// baseline (speedup 1.0000x reference)
#include <cuda_runtime.h>
#include <cuda_fp16.h>
#include <math_constants.h>
#include <cstdint>

#define N_PTS 16384
#define C_DIM 64
#define K_NN 16
#define SPLIT 8
#define SEG (N_PTS / SPLIT)
#define K_SEL 18
#define K_CAND (SPLIT * K_SEL)   // 144

__device__ float g_norms[N_PTS];
__device__ __half g_xh[N_PTS * C_DIM];
__device__ int g_pi[N_PTS * K_CAND];
__device__ int g_knn[N_PTS * K_NN];

// ---------------------------------------------------------------------------
// Kernel 0: norms + fp16 copy of x
// ---------------------------------------------------------------------------
__global__ __launch_bounds__(256) void prep_kernel(const float* __restrict__ x) {
    int i = blockIdx.x * 256 + threadIdx.x;
    const float4* xv = (const float4*)(x + (size_t)i * C_DIM);
    __half2* oh = (__half2*)(g_xh + (size_t)i * C_DIM);
    float s = 0.f;
#pragma unroll
    for (int d = 0; d < 16; ++d) {
        float4 v = xv[d];
        s += v.x * v.x + v.y * v.y + v.z * v.z + v.w * v.w;
        oh[2 * d]     = __floats2half2_rn(v.x, v.y);
        oh[2 * d + 1] = __floats2half2_rn(v.z, v.w);
    }
    g_norms[i] = s;
}

// ---------------------------------------------------------------------------
// Kernel 1: fp16 screen with packed u32 keys; top-18 per split.
// grid (128, 8) = 1024 CTAs x 128 thr; 7 CTAs/SM -> all co-resident.
// ---------------------------------------------------------------------------
#define QT 128
#define JT 128

__global__ __launch_bounds__(128, 7) void screen_kernel() {
    __shared__ __half sc[JT * C_DIM];   // 16 KB candidate tile
    __shared__ float sn[JT];

    int t = threadIdx.x;
    int q = blockIdx.x * QT + t;
    int s0 = blockIdx.y;

    __half2 xq[32];
    {
        const uint4* xv = (const uint4*)(g_xh + (size_t)q * C_DIM);
#pragma unroll
        for (int d = 0; d < 8; ++d) *(uint4*)&xq[4 * d] = xv[d];
    }
    float nq = g_norms[q];

    unsigned bd[K_SEL];
#pragma unroll
    for (int s = 0; s < K_SEL; ++s) bd[s] = 0xFFFFFFFFu;

    int jbeg = s0 * SEG, jend = jbeg + SEG;
    for (int jt = jbeg; jt < jend; jt += JT) {
        __syncthreads();
        const uint4* src = (const uint4*)(g_xh + (size_t)jt * C_DIM);
        uint4* dst = (uint4*)sc;
#pragma unroll
        for (int i = 0; i < 8; ++i) dst[t + i * 128] = src[t + i * 128];
        sn[t] = g_norms[jt + t];
        __syncthreads();

#pragma unroll 1
        for (int j = 0; j < JT; ++j) {
            const uint4* cr = (const uint4*)(sc + j * C_DIM);
            __half2 a0 = __float2half2_rn(0.f);
            __half2 a1 = a0, a2 = a0, a3 = a0;
#pragma unroll
            for (int d = 0; d < 8; ++d) {
                uint4 v = cr[d];                      // 4 half2, broadcast
                const __half2* cc = (const __half2*)&v;
                a0 = __hfma2(xq[4 * d],     cc[0], a0);
                a1 = __hfma2(xq[4 * d + 1], cc[1], a1);
                a2 = __hfma2(xq[4 * d + 2], cc[2], a2);
                a3 = __hfma2(xq[4 * d + 3], cc[3], a3);
            }
            __half2 h = __hadd2(__hadd2(a0, a1), __hadd2(a2, a3));
            float dot = __low2float(h) + __high2float(h);
            float m = fmaf(-2.f, dot, nq + sn[j]);
            unsigned key = ((unsigned)__half_as_ushort(__float2half_rn(m)) << 16)
                         | (unsigned)(jt + j);
            if (key < bd[K_SEL - 1]) {
                unsigned cur = key;
#pragma unroll
                for (int s = 0; s < K_SEL; ++s) {
                    unsigned lo = min(bd[s], cur);
                    cur = max(bd[s], cur);
                    bd[s] = lo;
                }
            }
        }
    }

    int lb = q * K_CAND + s0 * K_SEL;
#pragma unroll
    for (int s = 0; s < K_SEL; ++s) g_pi[lb + s] = (int)(bd[s] & 0xFFFFu);
}

// ---------------------------------------------------------------------------
// Kernel 2: exact fp32 rerank of 144 candidates -> top-16 set (warp/query)
// ---------------------------------------------------------------------------
__global__ __launch_bounds__(256) void rerank_kernel(const float* __restrict__ x) {
    int w = threadIdx.x >> 5, lane = threadIdx.x & 31;
    int q = blockIdx.x * 8 + w;
    const float4* xq = (const float4*)(x + (size_t)q * C_DIM);

    float dv[5]; int ci[5];
#pragma unroll
    for (int s = 0; s < 5; ++s) {
        int i = s * 32 + lane;
        int c = (i < K_CAND) ? g_pi[q * K_CAND + i] : q;
        if (c != q && i < K_CAND) {
            const float4* xc = (const float4*)(x + (size_t)c * C_DIM);
            float a0 = 0.f, a1 = 0.f, a2 = 0.f, a3 = 0.f;
#pragma unroll
            for (int d = 0; d < 16; ++d) {
                float4 u = xq[d], v = xc[d];
                a0 = fmaf(u.x, v.x, a0);
                a1 = fmaf(u.y, v.y, a1);
                a2 = fmaf(u.z, v.z, a2);
                a3 = fmaf(u.w, v.w, a3);
            }
            float dot = (a0 + a1) + (a2 + a3);
            dv[s] = g_norms[c] - 2.f * dot;     // nq const per q: rank-safe
            ci[s] = c;
        } else { dv[s] = CUDART_INF_F; ci[s] = -1; }
    }

#pragma unroll 1
    for (int s = 0; s < K_NN; ++s) {
        float m = dv[0]; int idx = ci[0], key = lane;
#pragma unroll
        for (int u = 1; u < 5; ++u)
            if (dv[u] < m) { m = dv[u]; idx = ci[u]; key = u * 32 + lane; }
#pragma unroll
        for (int off = 16; off > 0; off >>= 1) {
            float om = __shfl_xor_sync(0xffffffffu, m, off);
            int   oi = __shfl_xor_sync(0xffffffffu, idx, off);
            int   ok = __shfl_xor_sync(0xffffffffu, key, off);
            if (om < m || (om == m && ok < key)) { m = om; idx = oi; key = ok; }
        }
        if ((key & 31) == lane) {
            int slot = key >> 5;
            if (slot == 0) dv[0] = CUDART_INF_F;
            else if (slot == 1) dv[1] = CUDART_INF_F;
            else if (slot == 2) dv[2] = CUDART_INF_F;
            else if (slot == 3) dv[3] = CUDART_INF_F;
            else dv[4] = CUDART_INF_F;
        }
        if (lane == 0) g_knn[q * K_NN + s] = idx;
    }
}

// ---------------------------------------------------------------------------
// Kernel 3: factored edge-MLP (R11 exact config: full W in smem, tile 8).
// feat@W = x_i@W[0:64] (once per query) + (x_j - x_i)@W[64:128] per neighbor.
// ---------------------------------------------------------------------------
#define MLP_SMEM_FLOATS (32768 + 8 * 1088)   // W(128x256) + 8 x (64 + 16*64)

__global__ __launch_bounds__(256) void mlp_kernel(const float* __restrict__ x,
                                                  const float* __restrict__ W,
                                                  const float* __restrict__ b,
                                                  float* __restrict__ y) {
    extern __shared__ float fsm[];
    float* sW    = fsm;
    float* sfeat = fsm + 32768;

    int tid  = threadIdx.x;
    int warp = tid >> 5;
    int lane = tid & 31;

    {
        const float4* Wv = (const float4*)W;
        float4* sWv = (float4*)sW;
        for (int i = tid; i < 8192; i += 256) sWv[i] = Wv[i];
    }
    float bb[8];
#pragma unroll
    for (int k = 0; k < 8; ++k) bb[k] = b[lane * 8 + k];
    __syncthreads();

    float* f = sfeat + warp * 1088;           // [0:64]=x_i, then 16 x 64 diffs
    const float4* f4  = (const float4*)f;
    const float4* sW4 = (const float4*)sW;

    for (int qg = blockIdx.x; qg < N_PTS / 8; qg += gridDim.x) {
        int q = qg * 8 + warp;

        float xi0 = x[(size_t)q * 64 + lane];
        float xi1 = x[(size_t)q * 64 + 32 + lane];
        f[lane]      = xi0;
        f[32 + lane] = xi1;
#pragma unroll 1
        for (int n = 0; n < 16; ++n) {
            int j = g_knn[q * 16 + n];
            float v0 = x[(size_t)j * 64 + lane];
            float v1 = x[(size_t)j * 64 + 32 + lane];
            f[64 + n * 64 + lane]      = v0 - xi0;
            f[64 + n * 64 + 32 + lane] = v1 - xi1;
        }
        __syncwarp();

        // neighbor-invariant base: bb + x_i @ W[0:64]
        float base[8];
#pragma unroll
        for (int k = 0; k < 8; ++k) base[k] = bb[k];
#pragma unroll 2
        for (int d = 0; d < 64; d += 4) {
            float4 fe4 = f4[d >> 2];                         // broadcast
#pragma unroll
            for (int dd = 0; dd < 4; ++dd) {
                float4 w0 = sW4[(d + dd) * 64 + lane * 2];
                float4 w1 = sW4[(d + dd) * 64 + lane * 2 + 1];
                float fe = (dd == 0) ? fe4.x : (dd == 1) ? fe4.y
                         : (dd == 2) ? fe4.z : fe4.w;
                base[0] = fmaf(fe, w0.x, base[0]);
                base[1] = fmaf(fe, w0.y, base[1]);
                base[2] = fmaf(fe, w0.z, base[2]);
                base[3] = fmaf(fe, w0.w, base[3]);
                base[4] = fmaf(fe, w1.x, base[4]);
                base[5] = fmaf(fe, w1.y, base[5]);
                base[6] = fmaf(fe, w1.z, base[6]);
                base[7] = fmaf(fe, w1.w, base[7]);
            }
        }

        float vmax[8];
#pragma unroll
        for (int k = 0; k < 8; ++k) vmax[k] = 0.f;           // relu >= 0

#pragma unroll 1
        for (int ch = 0; ch < 2; ++ch) {                     // 8 neighbors/chunk
            float acc[8][8];
#pragma unroll
            for (int n = 0; n < 8; ++n)
#pragma unroll
                for (int k = 0; k < 8; ++k) acc[n][k] = base[k];

#pragma unroll 1
            for (int d = 0; d < 64; d += 4) {
                float4 fv[8];
#pragma unroll
                for (int n = 0; n < 8; ++n)
                    fv[n] = f4[16 + (ch * 8 + n) * 16 + (d >> 2)];   // broadcast
#pragma unroll
                for (int dd = 0; dd < 4; ++dd) {
                    float4 w0 = sW4[(64 + d + dd) * 64 + lane * 2];
                    float4 w1 = sW4[(64 + d + dd) * 64 + lane * 2 + 1];
#pragma unroll
                    for (int n = 0; n < 8; ++n) {
                        float fe = (dd == 0) ? fv[n].x : (dd == 1) ? fv[n].y
                                 : (dd == 2) ? fv[n].z : fv[n].w;
                        acc[n][0] = fmaf(fe, w0.x, acc[n][0]);
                        acc[n][1] = fmaf(fe, w0.y, acc[n][1]);
                        acc[n][2] = fmaf(fe, w0.z, acc[n][2]);
                        acc[n][3] = fmaf(fe, w0.w, acc[n][3]);
                        acc[n][4] = fmaf(fe, w1.x, acc[n][4]);
                        acc[n][5] = fmaf(fe, w1.y, acc[n][5]);
                        acc[n][6] = fmaf(fe, w1.z, acc[n][6]);
                        acc[n][7] = fmaf(fe, w1.w, acc[n][7]);
                    }
                }
            }
#pragma unroll
            for (int n = 0; n < 8; ++n)
#pragma unroll
                for (int k = 0; k < 8; ++k)
                    vmax[k] = fmaxf(vmax[k], fmaxf(acc[n][k], 0.f));
        }

        // m = lane*8+k ; c = m>>2 ; r = m&3 ; y[(q*4+r)*64 + c]
#pragma unroll
        for (int r = 0; r < 4; ++r) {
            float2 v = make_float2(vmax[r], vmax[4 + r]);
            ((float2*)(y + (size_t)(q * 4 + r) * 64))[lane] = v;
        }
        __syncwarp();
    }
}

// ---------------------------------------------------------------------------
extern "C" void kernel_launch(void* const* d_in, const int* in_sizes, int n_in,
                              void* d_out, int out_size) {
    const float* x = (const float*)d_in[0];
    const float* W = (const float*)d_in[1];
    const float* b = (const float*)d_in[2];
    float* y = (float*)d_out;

    prep_kernel<<<N_PTS / 256, 256>>>(x);

    dim3 sgrid(N_PTS / QT, SPLIT);
    screen_kernel<<<sgrid, QT>>>();

    rerank_kernel<<<N_PTS / 8, 256>>>(x);

    cudaFuncSetAttribute(mlp_kernel,
                         cudaFuncAttributeMaxDynamicSharedMemorySize,
                         MLP_SMEM_FLOATS * sizeof(float));
    mlp_kernel<<<148, 256, MLP_SMEM_FLOATS * sizeof(float)>>>(x, W, b, y);
}

// round 16
// speedup vs baseline: 1.0925x; 1.0925x over previous
#include <cuda_runtime.h>
#include <cuda_fp16.h>
#include <math_constants.h>
#include <cstdint>

#define N_PTS 16384
#define C_DIM 64
#define K_NN 16
#define SPLIT 4
#define SEG (N_PTS / SPLIT)
#define K_SEL 18
#define K_CAND (SPLIT * K_SEL)   // 72

__device__ float g_norms[N_PTS];
__device__ __half g_nh[N_PTS];
__device__ __half g_xh[N_PTS * C_DIM];
__device__ int g_pi[N_PTS * K_CAND];
__device__ int g_knn[N_PTS * K_NN];

// ---------------------------------------------------------------------------
// Kernel 0: norms (fp32 + fp16) + fp16 copy of x
// ---------------------------------------------------------------------------
__global__ __launch_bounds__(256) void prep_kernel(const float* __restrict__ x) {
    int i = blockIdx.x * 256 + threadIdx.x;
    const float4* xv = (const float4*)(x + (size_t)i * C_DIM);
    __half2* oh = (__half2*)(g_xh + (size_t)i * C_DIM);
    float s = 0.f;
#pragma unroll
    for (int d = 0; d < 16; ++d) {
        float4 v = xv[d];
        s += v.x * v.x + v.y * v.y + v.z * v.z + v.w * v.w;
        oh[2 * d]     = __floats2half2_rn(v.x, v.y);
        oh[2 * d + 1] = __floats2half2_rn(v.z, v.w);
    }
    g_norms[i] = s;
    g_nh[i] = __float2half(s);
}

// ---------------------------------------------------------------------------
// Kernel 1: fp16 screen, norm-folded accumulator init, packed u32 keys.
// grid (128, 4) = 512 CTAs x 128 thr, all co-resident (~3.5 CTAs/SM).
// Query pre-scaled by -2; a0 initialized with (nc, nq) so the HFMA2 chain
// directly yields m = nq + nc - 2*dot. Top-18 per split via IMNMX chain.
// ---------------------------------------------------------------------------
#define QT 128
#define JT 128

__global__ __launch_bounds__(128, 6) void screen_kernel() {
    __shared__ __half sc[JT * C_DIM];   // 16 KB candidate tile
    __shared__ __half snh[JT];

    int t = threadIdx.x;
    int q = blockIdx.x * QT + t;
    int s0 = blockIdx.y;

    __half2 xq[32];
    {
        const uint4* xv = (const uint4*)(g_xh + (size_t)q * C_DIM);
#pragma unroll
        for (int d = 0; d < 8; ++d) *(uint4*)&xq[4 * d] = xv[d];
        __half2 neg2 = __float2half2_rn(-2.f);
#pragma unroll
        for (int d = 0; d < 32; ++d) xq[d] = __hmul2(xq[d], neg2);
    }
    __half nqh = g_nh[q];

    unsigned bd[K_SEL];
#pragma unroll
    for (int s = 0; s < K_SEL; ++s) bd[s] = 0xFFFFFFFFu;

    int jbeg = s0 * SEG, jend = jbeg + SEG;
    for (int jt = jbeg; jt < jend; jt += JT) {
        __syncthreads();
        const uint4* src = (const uint4*)(g_xh + (size_t)jt * C_DIM);
        uint4* dst = (uint4*)sc;
#pragma unroll
        for (int i = 0; i < 8; ++i) dst[t + i * 128] = src[t + i * 128];
        snh[t] = g_nh[jt + t];
        __syncthreads();

#pragma unroll 1
        for (int j = 0; j < JT; ++j) {
            const uint4* cr = (const uint4*)(sc + j * C_DIM);
            __half2 a0 = __halves2half2(snh[j], nqh);     // norm fold
            __half2 z  = __float2half2_rn(0.f);
            __half2 a1 = z, a2 = z, a3 = z;
#pragma unroll
            for (int d = 0; d < 8; ++d) {
                uint4 v = cr[d];                      // 4 half2, broadcast
                const __half2* cc = (const __half2*)&v;
                a0 = __hfma2(xq[4 * d],     cc[0], a0);
                a1 = __hfma2(xq[4 * d + 1], cc[1], a1);
                a2 = __hfma2(xq[4 * d + 2], cc[2], a2);
                a3 = __hfma2(xq[4 * d + 3], cc[3], a3);
            }
            __half2 h = __hadd2(__hadd2(a0, a1), __hadd2(a2, a3));
            __half mh = __hadd(__low2half(h), __high2half(h));
            unsigned key = ((unsigned)__half_as_ushort(mh) << 16)
                         | (unsigned)(jt + j);
            if (key < bd[K_SEL - 1]) {
                unsigned cur = key;
#pragma unroll
                for (int s = 0; s < K_SEL; ++s) {
                    unsigned lo = min(bd[s], cur);
                    cur = max(bd[s], cur);
                    bd[s] = lo;
                }
            }
        }
    }

    int lb = q * K_CAND + s0 * K_SEL;
#pragma unroll
    for (int s = 0; s < K_SEL; ++s) g_pi[lb + s] = (int)(bd[s] & 0xFFFFu);
}

// ---------------------------------------------------------------------------
// Kernel 2: exact fp32 rerank of 72 candidates -> top-16 set (warp/query)
// ---------------------------------------------------------------------------
__global__ __launch_bounds__(256) void rerank_kernel(const float* __restrict__ x) {
    int w = threadIdx.x >> 5, lane = threadIdx.x & 31;
    int q = blockIdx.x * 8 + w;
    const float4* xq = (const float4*)(x + (size_t)q * C_DIM);

    float dv[3]; int ci[3];
#pragma unroll
    for (int s = 0; s < 3; ++s) {
        int i = s * 32 + lane;
        int c = (i < K_CAND) ? g_pi[q * K_CAND + i] : q;
        if (c != q && i < K_CAND) {
            const float4* xc = (const float4*)(x + (size_t)c * C_DIM);
            float a0 = 0.f, a1 = 0.f, a2 = 0.f, a3 = 0.f;
#pragma unroll
            for (int d = 0; d < 16; ++d) {
                float4 u = xq[d], v = xc[d];
                a0 = fmaf(u.x, v.x, a0);
                a1 = fmaf(u.y, v.y, a1);
                a2 = fmaf(u.z, v.z, a2);
                a3 = fmaf(u.w, v.w, a3);
            }
            float dot = (a0 + a1) + (a2 + a3);
            dv[s] = g_norms[c] - 2.f * dot;     // nq const per q: rank-safe
            ci[s] = c;
        } else { dv[s] = CUDART_INF_F; ci[s] = -1; }
    }

#pragma unroll 1
    for (int s = 0; s < K_NN; ++s) {
        float m = dv[0]; int idx = ci[0], key = lane;
#pragma unroll
        for (int u = 1; u < 3; ++u)
            if (dv[u] < m) { m = dv[u]; idx = ci[u]; key = u * 32 + lane; }
#pragma unroll
        for (int off = 16; off > 0; off >>= 1) {
            float om = __shfl_xor_sync(0xffffffffu, m, off);
            int   oi = __shfl_xor_sync(0xffffffffu, idx, off);
            int   ok = __shfl_xor_sync(0xffffffffu, key, off);
            if (om < m || (om == m && ok < key)) { m = om; idx = oi; key = ok; }
        }
        if ((key & 31) == lane) {
            int slot = key >> 5;
            if (slot == 0) dv[0] = CUDART_INF_F;
            else if (slot == 1) dv[1] = CUDART_INF_F;
            else dv[2] = CUDART_INF_F;
        }
        if (lane == 0) g_knn[q * K_NN + s] = idx;
    }
}

// ---------------------------------------------------------------------------
// Kernel 3: factored edge-MLP (R11 config: full W in smem, 8-neighbor tile).
// feat@W = x_i@W[0:64] (once per query) + (x_j - x_i)@W[64:128] per neighbor.
// ---------------------------------------------------------------------------
#define MLP_SMEM_FLOATS (32768 + 8 * 1088)   // W(128x256) + 8 x (64 + 16*64)

__global__ __launch_bounds__(256) void mlp_kernel(const float* __restrict__ x,
                                                  const float* __restrict__ W,
                                                  const float* __restrict__ b,
                                                  float* __restrict__ y) {
    extern __shared__ float fsm[];
    float* sW    = fsm;
    float* sfeat = fsm + 32768;

    int tid  = threadIdx.x;
    int warp = tid >> 5;
    int lane = tid & 31;

    {
        const float4* Wv = (const float4*)W;
        float4* sWv = (float4*)sW;
        for (int i = tid; i < 8192; i += 256) sWv[i] = Wv[i];
    }
    float bb[8];
#pragma unroll
    for (int k = 0; k < 8; ++k) bb[k] = b[lane * 8 + k];
    __syncthreads();

    float* f = sfeat + warp * 1088;           // [0:64]=x_i, then 16 x 64 diffs
    const float4* f4  = (const float4*)f;
    const float4* sW4 = (const float4*)sW;

    for (int qg = blockIdx.x; qg < N_PTS / 8; qg += gridDim.x) {
        int q = qg * 8 + warp;

        float xi0 = x[(size_t)q * 64 + lane];
        float xi1 = x[(size_t)q * 64 + 32 + lane];
        f[lane]      = xi0;
        f[32 + lane] = xi1;
#pragma unroll 1
        for (int n = 0; n < 16; ++n) {
            int j = g_knn[q * 16 + n];
            float v0 = x[(size_t)j * 64 + lane];
            float v1 = x[(size_t)j * 64 + 32 + lane];
            f[64 + n * 64 + lane]      = v0 - xi0;
            f[64 + n * 64 + 32 + lane] = v1 - xi1;
        }
        __syncwarp();

        // neighbor-invariant base: bb + x_i @ W[0:64]
        float base[8];
#pragma unroll
        for (int k = 0; k < 8; ++k) base[k] = bb[k];
#pragma unroll 2
        for (int d = 0; d < 64; d += 4) {
            float4 fe4 = f4[d >> 2];                         // broadcast
#pragma unroll
            for (int dd = 0; dd < 4; ++dd) {
                float4 w0 = sW4[(d + dd) * 64 + lane * 2];
                float4 w1 = sW4[(d + dd) * 64 + lane * 2 + 1];
                float fe = (dd == 0) ? fe4.x : (dd == 1) ? fe4.y
                         : (dd == 2) ? fe4.z : fe4.w;
                base[0] = fmaf(fe, w0.x, base[0]);
                base[1] = fmaf(fe, w0.y, base[1]);
                base[2] = fmaf(fe, w0.z, base[2]);
                base[3] = fmaf(fe, w0.w, base[3]);
                base[4] = fmaf(fe, w1.x, base[4]);
                base[5] = fmaf(fe, w1.y, base[5]);
                base[6] = fmaf(fe, w1.z, base[6]);
                base[7] = fmaf(fe, w1.w, base[7]);
            }
        }

        float vmax[8];
#pragma unroll
        for (int k = 0; k < 8; ++k) vmax[k] = 0.f;           // relu >= 0

#pragma unroll 1
        for (int ch = 0; ch < 2; ++ch) {                     // 8 neighbors/chunk
            float acc[8][8];
#pragma unroll
            for (int n = 0; n < 8; ++n)
#pragma unroll
                for (int k = 0; k < 8; ++k) acc[n][k] = base[k];

#pragma unroll 1
            for (int d = 0; d < 64; d += 4) {
                float4 fv[8];
#pragma unroll
                for (int n = 0; n < 8; ++n)
                    fv[n] = f4[16 + (ch * 8 + n) * 16 + (d >> 2)];   // broadcast
#pragma unroll
                for (int dd = 0; dd < 4; ++dd) {
                    float4 w0 = sW4[(64 + d + dd) * 64 + lane * 2];
                    float4 w1 = sW4[(64 + d + dd) * 64 + lane * 2 + 1];
#pragma unroll
                    for (int n = 0; n < 8; ++n) {
                        float fe = (dd == 0) ? fv[n].x : (dd == 1) ? fv[n].y
                                 : (dd == 2) ? fv[n].z : fv[n].w;
                        acc[n][0] = fmaf(fe, w0.x, acc[n][0]);
                        acc[n][1] = fmaf(fe, w0.y, acc[n][1]);
                        acc[n][2] = fmaf(fe, w0.z, acc[n][2]);
                        acc[n][3] = fmaf(fe, w0.w, acc[n][3]);
                        acc[n][4] = fmaf(fe, w1.x, acc[n][4]);
                        acc[n][5] = fmaf(fe, w1.y, acc[n][5]);
                        acc[n][6] = fmaf(fe, w1.z, acc[n][6]);
                        acc[n][7] = fmaf(fe, w1.w, acc[n][7]);
                    }
                }
            }
#pragma unroll
            for (int n = 0; n < 8; ++n)
#pragma unroll
                for (int k = 0; k < 8; ++k)
                    vmax[k] = fmaxf(vmax[k], fmaxf(acc[n][k], 0.f));
        }

        // m = lane*8+k ; c = m>>2 ; r = m&3 ; y[(q*4+r)*64 + c]
#pragma unroll
        for (int r = 0; r < 4; ++r) {
            float2 v = make_float2(vmax[r], vmax[4 + r]);
            ((float2*)(y + (size_t)(q * 4 + r) * 64))[lane] = v;
        }
        __syncwarp();
    }
}

// ---------------------------------------------------------------------------
extern "C" void kernel_launch(void* const* d_in, const int* in_sizes, int n_in,
                              void* d_out, int out_size) {
    const float* x = (const float*)d_in[0];
    const float* W = (const float*)d_in[1];
    const float* b = (const float*)d_in[2];
    float* y = (float*)d_out;

    prep_kernel<<<N_PTS / 256, 256>>>(x);

    dim3 sgrid(N_PTS / QT, SPLIT);
    screen_kernel<<<sgrid, QT>>>();

    rerank_kernel<<<N_PTS / 8, 256>>>(x);

    cudaFuncSetAttribute(mlp_kernel,
                         cudaFuncAttributeMaxDynamicSharedMemorySize,
                         MLP_SMEM_FLOATS * sizeof(float));
    mlp_kernel<<<148, 256, MLP_SMEM_FLOATS * sizeof(float)>>>(x, W, b, y);
}

// round 17
// speedup vs baseline: 1.1162x; 1.0217x over previous
#include <cuda_runtime.h>
#include <cuda_fp16.h>
#include <math_constants.h>
#include <cstdint>

#define N_PTS 16384
#define C_DIM 64
#define K_NN 16
#define SPLIT 4
#define SEG (N_PTS / SPLIT)
#define K_SEL 18
#define K_CAND (SPLIT * K_SEL)   // 72

__device__ float g_norms[N_PTS];
__device__ __half g_nh[N_PTS];
__device__ __half g_xh[N_PTS * C_DIM];
__device__ int g_pi[N_PTS * K_CAND];
__device__ int g_knn[N_PTS * K_NN];

// ---------------------------------------------------------------------------
// Kernel 0: norms (fp32 + fp16) + fp16 copy of x
// ---------------------------------------------------------------------------
__global__ __launch_bounds__(256) void prep_kernel(const float* __restrict__ x) {
    int i = blockIdx.x * 256 + threadIdx.x;
    const float4* xv = (const float4*)(x + (size_t)i * C_DIM);
    __half2* oh = (__half2*)(g_xh + (size_t)i * C_DIM);
    float s = 0.f;
#pragma unroll
    for (int d = 0; d < 16; ++d) {
        float4 v = xv[d];
        s += v.x * v.x + v.y * v.y + v.z * v.z + v.w * v.w;
        oh[2 * d]     = __floats2half2_rn(v.x, v.y);
        oh[2 * d + 1] = __floats2half2_rn(v.z, v.w);
    }
    g_norms[i] = s;
    g_nh[i] = __float2half(s);
}

// ---------------------------------------------------------------------------
// Kernel 1: fp16 screen, norm-folded accumulator init, packed u32 keys.
// (R16 winner, unchanged.)
// ---------------------------------------------------------------------------
#define QT 128
#define JT 128

__global__ __launch_bounds__(128, 6) void screen_kernel() {
    __shared__ __half sc[JT * C_DIM];   // 16 KB candidate tile
    __shared__ __half snh[JT];

    int t = threadIdx.x;
    int q = blockIdx.x * QT + t;
    int s0 = blockIdx.y;

    __half2 xq[32];
    {
        const uint4* xv = (const uint4*)(g_xh + (size_t)q * C_DIM);
#pragma unroll
        for (int d = 0; d < 8; ++d) *(uint4*)&xq[4 * d] = xv[d];
        __half2 neg2 = __float2half2_rn(-2.f);
#pragma unroll
        for (int d = 0; d < 32; ++d) xq[d] = __hmul2(xq[d], neg2);
    }
    __half nqh = g_nh[q];

    unsigned bd[K_SEL];
#pragma unroll
    for (int s = 0; s < K_SEL; ++s) bd[s] = 0xFFFFFFFFu;

    int jbeg = s0 * SEG, jend = jbeg + SEG;
    for (int jt = jbeg; jt < jend; jt += JT) {
        __syncthreads();
        const uint4* src = (const uint4*)(g_xh + (size_t)jt * C_DIM);
        uint4* dst = (uint4*)sc;
#pragma unroll
        for (int i = 0; i < 8; ++i) dst[t + i * 128] = src[t + i * 128];
        snh[t] = g_nh[jt + t];
        __syncthreads();

#pragma unroll 1
        for (int j = 0; j < JT; ++j) {
            const uint4* cr = (const uint4*)(sc + j * C_DIM);
            __half2 a0 = __halves2half2(snh[j], nqh);     // norm fold
            __half2 z  = __float2half2_rn(0.f);
            __half2 a1 = z, a2 = z, a3 = z;
#pragma unroll
            for (int d = 0; d < 8; ++d) {
                uint4 v = cr[d];                      // 4 half2, broadcast
                const __half2* cc = (const __half2*)&v;
                a0 = __hfma2(xq[4 * d],     cc[0], a0);
                a1 = __hfma2(xq[4 * d + 1], cc[1], a1);
                a2 = __hfma2(xq[4 * d + 2], cc[2], a2);
                a3 = __hfma2(xq[4 * d + 3], cc[3], a3);
            }
            __half2 h = __hadd2(__hadd2(a0, a1), __hadd2(a2, a3));
            __half mh = __hadd(__low2half(h), __high2half(h));
            unsigned key = ((unsigned)__half_as_ushort(mh) << 16)
                         | (unsigned)(jt + j);
            if (key < bd[K_SEL - 1]) {
                unsigned cur = key;
#pragma unroll
                for (int s = 0; s < K_SEL; ++s) {
                    unsigned lo = min(bd[s], cur);
                    cur = max(bd[s], cur);
                    bd[s] = lo;
                }
            }
        }
    }

    int lb = q * K_CAND + s0 * K_SEL;
#pragma unroll
    for (int s = 0; s < K_SEL; ++s) g_pi[lb + s] = (int)(bd[s] & 0xFFFFu);
}

// ---------------------------------------------------------------------------
// Kernel 2: exact fp32 rerank of 72 candidates -> top-16 set (R16, unchanged)
// ---------------------------------------------------------------------------
__global__ __launch_bounds__(256) void rerank_kernel(const float* __restrict__ x) {
    int w = threadIdx.x >> 5, lane = threadIdx.x & 31;
    int q = blockIdx.x * 8 + w;
    const float4* xq = (const float4*)(x + (size_t)q * C_DIM);

    float dv[3]; int ci[3];
#pragma unroll
    for (int s = 0; s < 3; ++s) {
        int i = s * 32 + lane;
        int c = (i < K_CAND) ? g_pi[q * K_CAND + i] : q;
        if (c != q && i < K_CAND) {
            const float4* xc = (const float4*)(x + (size_t)c * C_DIM);
            float a0 = 0.f, a1 = 0.f, a2 = 0.f, a3 = 0.f;
#pragma unroll
            for (int d = 0; d < 16; ++d) {
                float4 u = xq[d], v = xc[d];
                a0 = fmaf(u.x, v.x, a0);
                a1 = fmaf(u.y, v.y, a1);
                a2 = fmaf(u.z, v.z, a2);
                a3 = fmaf(u.w, v.w, a3);
            }
            float dot = (a0 + a1) + (a2 + a3);
            dv[s] = g_norms[c] - 2.f * dot;     // nq const per q: rank-safe
            ci[s] = c;
        } else { dv[s] = CUDART_INF_F; ci[s] = -1; }
    }

#pragma unroll 1
    for (int s = 0; s < K_NN; ++s) {
        float m = dv[0]; int idx = ci[0], key = lane;
#pragma unroll
        for (int u = 1; u < 3; ++u)
            if (dv[u] < m) { m = dv[u]; idx = ci[u]; key = u * 32 + lane; }
#pragma unroll
        for (int off = 16; off > 0; off >>= 1) {
            float om = __shfl_xor_sync(0xffffffffu, m, off);
            int   oi = __shfl_xor_sync(0xffffffffu, idx, off);
            int   ok = __shfl_xor_sync(0xffffffffu, key, off);
            if (om < m || (om == m && ok < key)) { m = om; idx = oi; key = ok; }
        }
        if ((key & 31) == lane) {
            int slot = key >> 5;
            if (slot == 0) dv[0] = CUDART_INF_F;
            else if (slot == 1) dv[1] = CUDART_INF_F;
            else dv[2] = CUDART_INF_F;
        }
        if (lane == 0) g_knn[q * K_NN + s] = idx;
    }
}

// ---------------------------------------------------------------------------
// Kernel 3: factored edge-MLP, fp16 bottom GEMM.
//   base = b + x_i @ W_top            (fp32, neighbor-invariant, per query)
//   h    = base + diff @ W_bot        (HFMA2, 2 cols/reg, fp32 promote /16 dims)
// smem: W_top fp32 64KB + W_bot fp16 32KB + per-warp feat ~18KB = ~114KB.
// ---------------------------------------------------------------------------
#define WARP_FEAT 576                         // 64 fp32 x_i + 512 half2 diffs
#define MLP_SMEM_FLOATS (16384 + 8192 + 8 * WARP_FEAT)

__global__ __launch_bounds__(256) void mlp_kernel(const float* __restrict__ x,
                                                  const float* __restrict__ W,
                                                  const float* __restrict__ b,
                                                  float* __restrict__ y) {
    extern __shared__ float fsm[];
    float*   sWt = fsm;                        // W rows 0..63, fp32 (64x256)
    __half2* sWb = (__half2*)(fsm + 16384);    // W rows 64..127, fp16 (64x128 h2)
    float*   sft = fsm + 16384 + 8192;         // per-warp feat blocks

    int tid  = threadIdx.x;
    int warp = tid >> 5;
    int lane = tid & 31;

    {   // stage W_top fp32
        const float4* Wv = (const float4*)W;
        float4* sWv = (float4*)sWt;
        for (int i = tid; i < 4096; i += 256) sWv[i] = Wv[i];
        // stage W_bot fp16: row r (0..63) = W[64+r], 128 half2 per row
        const float2* Wf2 = (const float2*)W;
        for (int i = tid; i < 8192; i += 256) {
            float2 wv = Wf2[(64 + (i >> 7)) * 128 + (i & 127)];
            sWb[i] = __floats2half2_rn(wv.x, wv.y);
        }
    }
    float bb[8];
#pragma unroll
    for (int k = 0; k < 8; ++k) bb[k] = b[lane * 8 + k];
    __syncthreads();

    float*   fxi  = sft + warp * WARP_FEAT;            // 64 fp32
    __half2* sdif = (__half2*)(fxi + 64);              // 16 x 32 half2
    const float4* f4  = (const float4*)fxi;
    const float4* sW4 = (const float4*)sWt;

    for (int qg = blockIdx.x; qg < N_PTS / 8; qg += gridDim.x) {
        int q = qg * 8 + warp;

        float2 xi2 = ((const float2*)(x + (size_t)q * 64))[lane];  // dims 2l,2l+1
        fxi[2 * lane]     = xi2.x;
        fxi[2 * lane + 1] = xi2.y;
#pragma unroll 1
        for (int n = 0; n < 16; ++n) {
            int j = g_knn[q * 16 + n];
            float2 v2 = ((const float2*)(x + (size_t)j * 64))[lane];
            sdif[n * 32 + lane] = __floats2half2_rn(v2.x - xi2.x, v2.y - xi2.y);
        }
        __syncwarp();

        // neighbor-invariant base: bb + x_i @ W_top (fp32)
        float base[8];
#pragma unroll
        for (int k = 0; k < 8; ++k) base[k] = bb[k];
#pragma unroll 2
        for (int d = 0; d < 64; d += 4) {
            float4 fe4 = f4[d >> 2];                         // broadcast
#pragma unroll
            for (int dd = 0; dd < 4; ++dd) {
                float4 w0 = sW4[(d + dd) * 64 + lane * 2];
                float4 w1 = sW4[(d + dd) * 64 + lane * 2 + 1];
                float fe = (dd == 0) ? fe4.x : (dd == 1) ? fe4.y
                         : (dd == 2) ? fe4.z : fe4.w;
                base[0] = fmaf(fe, w0.x, base[0]);
                base[1] = fmaf(fe, w0.y, base[1]);
                base[2] = fmaf(fe, w0.z, base[2]);
                base[3] = fmaf(fe, w0.w, base[3]);
                base[4] = fmaf(fe, w1.x, base[4]);
                base[5] = fmaf(fe, w1.y, base[5]);
                base[6] = fmaf(fe, w1.z, base[6]);
                base[7] = fmaf(fe, w1.w, base[7]);
            }
        }

        float vmax[8];
#pragma unroll
        for (int k = 0; k < 8; ++k) vmax[k] = 0.f;           // relu >= 0

#pragma unroll 1
        for (int ch = 0; ch < 2; ++ch) {                     // 8 neighbors/chunk
            float accf[8][8];
#pragma unroll
            for (int n = 0; n < 8; ++n)
#pragma unroll
                for (int k = 0; k < 8; ++k) accf[n][k] = base[k];

#pragma unroll 1
            for (int c = 0; c < 4; ++c) {                    // 16-dim chunks
                __half2 a16[8][4];
                __half2 z = __float2half2_rn(0.f);
#pragma unroll
                for (int n = 0; n < 8; ++n)
#pragma unroll
                    for (int k = 0; k < 4; ++k) a16[n][k] = z;

#pragma unroll
                for (int dh = 0; dh < 8; ++dh) {
                    int d2 = c * 8 + dh;                     // half2 dim pair
                    uint4 wl = ((const uint4*)(sWb + (2 * d2) * 128))[lane];
                    uint4 wh = ((const uint4*)(sWb + (2 * d2 + 1) * 128))[lane];
                    const __half2* wl2 = (const __half2*)&wl;
                    const __half2* wh2 = (const __half2*)&wh;
#pragma unroll
                    for (int n = 0; n < 8; ++n) {
                        __half2 fv = sdif[(ch * 8 + n) * 32 + d2];  // broadcast
                        __half2 flo = __low2half2(fv);    // -> .H0_H0 selector
                        __half2 fhi = __high2half2(fv);   // -> .H1_H1 selector
                        a16[n][0] = __hfma2(flo, wl2[0], a16[n][0]);
                        a16[n][1] = __hfma2(flo, wl2[1], a16[n][1]);
                        a16[n][2] = __hfma2(flo, wl2[2], a16[n][2]);
                        a16[n][3] = __hfma2(flo, wl2[3], a16[n][3]);
                        a16[n][0] = __hfma2(fhi, wh2[0], a16[n][0]);
                        a16[n][1] = __hfma2(fhi, wh2[1], a16[n][1]);
                        a16[n][2] = __hfma2(fhi, wh2[2], a16[n][2]);
                        a16[n][3] = __hfma2(fhi, wh2[3], a16[n][3]);
                    }
                }
                // promote chunk to fp32
#pragma unroll
                for (int n = 0; n < 8; ++n)
#pragma unroll
                    for (int k = 0; k < 4; ++k) {
                        float2 p = __half22float2(a16[n][k]);
                        accf[n][2 * k]     += p.x;
                        accf[n][2 * k + 1] += p.y;
                    }
            }
#pragma unroll
            for (int n = 0; n < 8; ++n)
#pragma unroll
                for (int k = 0; k < 8; ++k)
                    vmax[k] = fmaxf(vmax[k], fmaxf(accf[n][k], 0.f));
        }

        // m = lane*8+k ; c = m>>2 ; r = m&3 ; y[(q*4+r)*64 + c]
#pragma unroll
        for (int r = 0; r < 4; ++r) {
            float2 v = make_float2(vmax[r], vmax[4 + r]);
            ((float2*)(y + (size_t)(q * 4 + r) * 64))[lane] = v;
        }
        __syncwarp();
    }
}

// ---------------------------------------------------------------------------
extern "C" void kernel_launch(void* const* d_in, const int* in_sizes, int n_in,
                              void* d_out, int out_size) {
    const float* x = (const float*)d_in[0];
    const float* W = (const float*)d_in[1];
    const float* b = (const float*)d_in[2];
    float* y = (float*)d_out;

    prep_kernel<<<N_PTS / 256, 256>>>(x);

    dim3 sgrid(N_PTS / QT, SPLIT);
    screen_kernel<<<sgrid, QT>>>();

    rerank_kernel<<<N_PTS / 8, 256>>>(x);

    cudaFuncSetAttribute(mlp_kernel,
                         cudaFuncAttributeMaxDynamicSharedMemorySize,
                         MLP_SMEM_FLOATS * sizeof(float));
    mlp_kernel<<<148, 256, MLP_SMEM_FLOATS * sizeof(float)>>>(x, W, b, y);
}